// round 13
// baseline (speedup 1.0000x reference)
#include <cuda_runtime.h>
#include <cuda_bf16.h>
#include <math.h>
#include <stdint.h>

#define DI   1536
#define DM   768
#define NST  16
#define DTR  48
#define BB   2
#define LL   1024
#define NSEG 32
#define SEGL (LL / NSEG)

// ---------------- scratch (device globals; no allocation allowed) ----------------
__device__ float g_xz[(size_t)BB * LL * 2 * DI];      // in_proj output (x | z)
__device__ float g_xc0[(size_t)BB * LL * DI];         // conv+silu fwd (f32, for scans)
__device__ float g_xc1[(size_t)BB * LL * DI];
__device__ float g_xdbl0[(size_t)BB * LL * 80];       // x_proj out (summed): [dt|B|C]
__device__ float g_xdbl1[(size_t)BB * LL * 80];
__device__ float g_delta0[(size_t)BB * LL * DI];
__device__ float g_delta1[(size_t)BB * LL * DI];
__device__ float g_segP0[(size_t)BB * NSEG * DI * NST];   // pass A: P; pass B overwrites with start state
__device__ float g_segP1[(size_t)BB * NSEG * DI * NST];
__device__ float g_segH0[(size_t)BB * NSEG * DI * NST];
__device__ float g_segH1[(size_t)BB * NSEG * DI * NST];
__device__ float g_ys1[(size_t)BB * LL * DI];         // rev branch pre-gate partial (unflipped)
__device__ float g_xdblp[(size_t)8 * BB * LL * 80];   // x_proj partials [br*4+kq]

// bf16 hi/lo pre-split buffers
__device__ uint16_t g_hidh[(size_t)BB * LL * DM],     g_hidl[(size_t)BB * LL * DM];
__device__ uint16_t g_w1h[(size_t)2 * DI * DM],       g_w1l[(size_t)2 * DI * DM];
__device__ uint16_t g_xc0h[(size_t)BB * LL * DI],     g_xc0l[(size_t)BB * LL * DI];
__device__ uint16_t g_xc1h[(size_t)BB * LL * DI],     g_xc1l[(size_t)BB * LL * DI];
__device__ uint16_t g_xwh[(size_t)2 * 80 * DI],       g_xwl[(size_t)2 * 80 * DI];
__device__ uint16_t g_dtwh[(size_t)2 * DI * DTR],     g_dtwl[(size_t)2 * DI * DTR];
__device__ uint16_t g_owh[(size_t)DM * DI],           g_owl[(size_t)DM * DI];
__device__ uint16_t g_xdh[(size_t)2 * BB * LL * 80],  g_xdl[(size_t)2 * BB * LL * 80];
__device__ uint16_t g_ysh[(size_t)BB * LL * DI],      g_ysl[(size_t)BB * LL * DI];

// =================== helpers ===================
__device__ __forceinline__ uint32_t smem_u32(const void* p) {
    uint32_t a;
    asm("{ .reg .u64 t; cvta.to.shared.u64 t, %1; cvt.u32.u64 %0, t; }" : "=r"(a) : "l"(p));
    return a;
}
#define SWZ128(x) ((x) ^ (((x) >> 3) & 0x70))

__device__ __forceinline__ void split2(float a0, float a1, uint32_t& hi, uint32_t& lo) {
    asm("cvt.rn.bf16x2.f32 %0, %1, %2;" : "=r"(hi) : "f"(a1), "f"(a0));
    float h0 = __uint_as_float(hi << 16);
    float h1 = __uint_as_float(hi & 0xffff0000u);
    float r0 = a0 - h0, r1 = a1 - h1;
    asm("cvt.rn.bf16x2.f32 %0, %1, %2;" : "=r"(lo) : "f"(r1), "f"(r0));
}

__device__ __forceinline__ void split_g(uint16_t* hi, uint16_t* lo, size_t j, float4 v) {
    uint32_t h01, l01, h23, l23;
    split2(v.x, v.y, h01, l01);
    split2(v.z, v.w, h23, l23);
    *(uint2*)(hi + j) = make_uint2(h01, h23);
    *(uint2*)(lo + j) = make_uint2(l01, l23);
}

#define LDSM_X4(r0, r1, r2, r3, a) \
    asm volatile("ldmatrix.sync.aligned.m8n8.x4.shared.b16 {%0,%1,%2,%3}, [%4];" \
                 : "=r"(r0), "=r"(r1), "=r"(r2), "=r"(r3) : "r"(a))
#define LDSM_X2(r0, r1, a) \
    asm volatile("ldmatrix.sync.aligned.m8n8.x2.shared.b16 {%0,%1}, [%2];" \
                 : "=r"(r0), "=r"(r1) : "r"(a))
#define MMA16816(c, a, b) \
    asm volatile("mma.sync.aligned.m16n8k16.row.col.f32.bf16.bf16.f32 " \
                 "{%0,%1,%2,%3}, {%4,%5,%6,%7}, {%8,%9}, {%0,%1,%2,%3};" \
                 : "+f"((c)[0]), "+f"((c)[1]), "+f"((c)[2]), "+f"((c)[3]) \
                 : "r"((a)[0]), "r"((a)[1]), "r"((a)[2]), "r"((a)[3]), \
                   "r"((b)[0]), "r"((b)[1]))
#define STS128U(addr, v) \
    asm volatile("st.shared.v4.b32 [%0], {%1,%2,%3,%4};" \
                 :: "r"(addr), "r"((v).x), "r"((v).y), "r"((v).z), "r"((v).w) : "memory")

__device__ __forceinline__ float silu_f(float v) {
    return v / (1.f + __expf(-v));
}
__device__ __forceinline__ float softplus_f(float v) {
    return fmaxf(v, 0.f) + __logf(1.f + __expf(-fabsf(v)));
}

// =================== split_many: pre-split static tensors ===================
struct SSeg { const float* src; uint16_t* hi; uint16_t* lo; int base4; int n4; };
struct SArgs { SSeg s[7]; int total4; };

__global__ void __launch_bounds__(256) split_many(SArgs a) {
    int idx = blockIdx.x * 256 + threadIdx.x;
    if (idx >= a.total4) return;
#pragma unroll
    for (int k = 0; k < 7; k++) {
        int j = idx - a.s[k].base4;
        if (j >= 0 && j < a.s[k].n4) {
            float4 v = *(const float4*)(a.s[k].src + (size_t)j * 4);
            split_g(a.s[k].hi, a.s[k].lo, (size_t)j * 4, v);
            return;
        }
    }
}

// =================== NT GEMM 128xBN (bf16 pre-split, single-buffer pipeline) ===================
struct TBArgs {
    const uint16_t* Ah; const uint16_t* Al;
    const uint16_t* Bh; const uint16_t* Bl;
    float* C; int K, lda, ldb, ldc;
};

template <int BN>
__global__ void __launch_bounds__(256) gemm_mma_s(TBArgs g) {
    extern __shared__ char smem[];
    const uint32_t sb = smem_u32(smem);
    constexpr int NT = BN / 16;
    constexpr int BHOFF = 32768;
    constexpr int BLOFF = 32768 + BN * 128;
    constexpr int BITER = (BN * 8) / 256;

    const int tid  = threadIdx.x;
    const int wid  = tid >> 5;
    const int lane = tid & 31;
    const int wm   = wid & 3;
    const int wn   = wid >> 2;
    const int bm = blockIdx.y * 128;
    const int bn = blockIdx.x * BN;

    uint4 rah[4], ral[4], rbh[BITER], rbl[BITER];
    float acc[2][NT][4];
#pragma unroll
    for (int mt = 0; mt < 2; mt++)
#pragma unroll
        for (int nt = 0; nt < NT; nt++)
#pragma unroll
            for (int q = 0; q < 4; q++) acc[mt][nt][q] = 0.f;

    auto ldg_tile = [&](int k0) {
#pragma unroll
        for (int t = 0; t < 4; t++) {
            int i = tid + t * 256;
            int r = i >> 3, q = i & 7;
            size_t ao = (size_t)(bm + r) * g.lda + k0 + q * 8;
            rah[t] = *(const uint4*)(g.Ah + ao);
            ral[t] = *(const uint4*)(g.Al + ao);
        }
#pragma unroll
        for (int t = 0; t < BITER; t++) {
            int i = tid + t * 256;
            int r = i >> 3, q = i & 7;
            size_t bo = (size_t)(bn + r) * g.ldb + k0 + q * 8;
            rbh[t] = *(const uint4*)(g.Bh + bo);
            rbl[t] = *(const uint4*)(g.Bl + bo);
        }
    };
    auto sts_tile = [&]() {
#pragma unroll
        for (int t = 0; t < 4; t++) {
            int i = tid + t * 256;
            int r = i >> 3, q = i & 7;
            uint32_t off = SWZ128((uint32_t)(r * 128 + q * 16));
            STS128U(sb + off, rah[t]);
            STS128U(sb + 16384 + off, ral[t]);
        }
#pragma unroll
        for (int t = 0; t < BITER; t++) {
            int i = tid + t * 256;
            int r = i >> 3, q = i & 7;
            uint32_t off = SWZ128((uint32_t)(r * 128 + q * 16));
            STS128U(sb + BHOFF + off, rbh[t]);
            STS128U(sb + BLOFF + off, rbl[t]);
        }
    };

    const int a_row = wm * 32 + (lane & 7) + ((lane >> 3) & 1) * 8;
    const int a_kc8 = (lane >> 4) * 8;
    const int b_row = wn * (BN / 2) + (lane & 7);
    const int b_kc8 = ((lane >> 3) & 1) * 8;

    auto compute = [&]() {
#pragma unroll
        for (int ks = 0; ks < 4; ks++) {
            const int k0 = ks * 16;
            uint32_t ahi[2][4], alo[2][4];
#pragma unroll
            for (int mt = 0; mt < 2; mt++) {
                uint32_t off = SWZ128((uint32_t)((a_row + mt * 16) * 128 + (k0 + a_kc8) * 2));
                LDSM_X4(ahi[mt][0], ahi[mt][1], ahi[mt][2], ahi[mt][3], sb + off);
                LDSM_X4(alo[mt][0], alo[mt][1], alo[mt][2], alo[mt][3], sb + 16384 + off);
            }
#pragma unroll
            for (int nt = 0; nt < NT; nt++) {
                uint32_t off = SWZ128((uint32_t)((b_row + nt * 8) * 128 + (k0 + b_kc8) * 2));
                uint32_t bhi[2], blo[2];
                LDSM_X2(bhi[0], bhi[1], sb + BHOFF + off);
                LDSM_X2(blo[0], blo[1], sb + BLOFF + off);
#pragma unroll
                for (int mt = 0; mt < 2; mt++) {
                    MMA16816(acc[mt][nt], ahi[mt], bhi);
                    MMA16816(acc[mt][nt], ahi[mt], blo);
                    MMA16816(acc[mt][nt], alo[mt], bhi);
                }
            }
        }
    };

    const int nk = g.K >> 6;
    ldg_tile(0);
    sts_tile();
    __syncthreads();
    for (int kt = 1; kt < nk; kt++) {
        ldg_tile(kt << 6);
        compute();
        __syncthreads();
        sts_tile();
        __syncthreads();
    }
    compute();

    const int er = lane >> 2;
    const int ec = (lane & 3) * 2;
#pragma unroll
    for (int mt = 0; mt < 2; mt++) {
        const int m = bm + wm * 32 + mt * 16 + er;
#pragma unroll
        for (int nt = 0; nt < NT; nt++) {
            const int n = bn + wn * (BN / 2) + nt * 8 + ec;
            *(float2*)(g.C + (size_t)m * g.ldc + n) =
                make_float2(acc[mt][nt][0], acc[mt][nt][1]);
            *(float2*)(g.C + (size_t)(m + 8) * g.ldc + n) =
                make_float2(acc[mt][nt][2], acc[mt][nt][3]);
        }
    }
}

// =================== x_proj GEMM: BM=64, split-K(4), single buffer ===================
struct G80B { const uint16_t* Ah[2]; const uint16_t* Al[2]; };

#define MMA80_SMEM 36864

__global__ void __launch_bounds__(256) gemm_mma80b(G80B g) {
    extern __shared__ char smem[];
    const uint32_t sb = smem_u32(smem);
    const int br = blockIdx.z >> 2;
    const int kq = blockIdx.z & 3;
    const uint16_t* __restrict__ Ah = g.Ah[br];
    const uint16_t* __restrict__ Al = g.Al[br];
    const uint16_t* __restrict__ Bh = g_xwh + (size_t)br * 80 * DI;
    const uint16_t* __restrict__ Bl = g_xwl + (size_t)br * 80 * DI;
    float* __restrict__ C = g_xdblp + (size_t)(br * 4 + kq) * BB * LL * 80;

    const int tid  = threadIdx.x;
    const int wid  = tid >> 5;
    const int lane = tid & 31;
    const int wm   = wid & 3;
    const int wn   = wid >> 2;
    const int bm = blockIdx.y * 64;
    const int kbase = kq * 384;

    uint4 rah[2], ral[2], rbh[3], rbl[3];
    float acc[5][4];
#pragma unroll
    for (int nt = 0; nt < 5; nt++)
#pragma unroll
        for (int q = 0; q < 4; q++) acc[nt][q] = 0.f;

    auto ldg_tile = [&](int k0) {
#pragma unroll
        for (int t = 0; t < 2; t++) {
            int i = tid + t * 256;
            int r = i >> 3, q = i & 7;
            size_t ao = (size_t)(bm + r) * DI + k0 + q * 8;
            rah[t] = *(const uint4*)(Ah + ao);
            ral[t] = *(const uint4*)(Al + ao);
        }
#pragma unroll
        for (int t = 0; t < 3; t++) {
            int i = tid + t * 256;
            if (i < 640) {
                int r = i >> 3, q = i & 7;
                size_t bo = (size_t)r * DI + k0 + q * 8;
                rbh[t] = *(const uint4*)(Bh + bo);
                rbl[t] = *(const uint4*)(Bl + bo);
            }
        }
    };
    auto sts_tile = [&]() {
#pragma unroll
        for (int t = 0; t < 2; t++) {
            int i = tid + t * 256;
            int r = i >> 3, q = i & 7;
            uint32_t off = SWZ128((uint32_t)(r * 128 + q * 16));
            STS128U(sb + off, rah[t]);
            STS128U(sb + 8192 + off, ral[t]);
        }
#pragma unroll
        for (int t = 0; t < 3; t++) {
            int i = tid + t * 256;
            if (i < 640) {
                int r = i >> 3, q = i & 7;
                uint32_t off = SWZ128((uint32_t)(r * 128 + q * 16));
                STS128U(sb + 16384 + off, rbh[t]);
                STS128U(sb + 26624 + off, rbl[t]);
            }
        }
    };

    const int a_row = wm * 16 + (lane & 7) + ((lane >> 3) & 1) * 8;
    const int a_kc8 = (lane >> 4) * 8;
    const int b_row = wn * 40 + (lane & 7);
    const int b_kc8 = ((lane >> 3) & 1) * 8;

    auto compute = [&]() {
#pragma unroll
        for (int ks = 0; ks < 4; ks++) {
            const int k0 = ks * 16;
            uint32_t ahi[4], alo[4];
            {
                uint32_t off = SWZ128((uint32_t)(a_row * 128 + (k0 + a_kc8) * 2));
                LDSM_X4(ahi[0], ahi[1], ahi[2], ahi[3], sb + off);
                LDSM_X4(alo[0], alo[1], alo[2], alo[3], sb + 8192 + off);
            }
#pragma unroll
            for (int nt = 0; nt < 5; nt++) {
                uint32_t off = SWZ128((uint32_t)((b_row + nt * 8) * 128 + (k0 + b_kc8) * 2));
                uint32_t bhi[2], blo[2];
                LDSM_X2(bhi[0], bhi[1], sb + 16384 + off);
                LDSM_X2(blo[0], blo[1], sb + 26624 + off);
                MMA16816(acc[nt], ahi, bhi);
                MMA16816(acc[nt], ahi, blo);
                MMA16816(acc[nt], alo, bhi);
            }
        }
    };

    const int nk = 384 >> 6;
    ldg_tile(kbase);
    sts_tile();
    __syncthreads();
    for (int kt = 1; kt < nk; kt++) {
        ldg_tile(kbase + (kt << 6));
        compute();
        __syncthreads();
        sts_tile();
        __syncthreads();
    }
    compute();

    const int er = lane >> 2;
    const int ec = (lane & 3) * 2;
    const int m = bm + wm * 16 + er;
#pragma unroll
    for (int nt = 0; nt < 5; nt++) {
        const int n = wn * 40 + nt * 8 + ec;
        *(float2*)(C + (size_t)m * 80 + n) = make_float2(acc[nt][0], acc[nt][1]);
        *(float2*)(C + (size_t)(m + 8) * 80 + n) = make_float2(acc[nt][2], acc[nt][3]);
    }
}

// =================== xdbl combine ===================
__global__ void __launch_bounds__(256) xdbl_combine() {
    const int n4 = (BB * LL * 80) / 4;
    int idx = blockIdx.x * 256 + threadIdx.x;
    if (idx >= 2 * n4) return;
    int br = idx >= n4;
    size_t j = (size_t)(idx - br * n4) * 4;
    float4 s = make_float4(0.f, 0.f, 0.f, 0.f);
#pragma unroll
    for (int k = 0; k < 4; k++) {
        float4 a = *(const float4*)(g_xdblp + (size_t)(br * 4 + k) * BB * LL * 80 + j);
        s.x += a.x; s.y += a.y; s.z += a.z; s.w += a.w;
    }
    float* dst = br ? g_xdbl1 : g_xdbl0;
    *(float4*)(dst + j) = s;
    split_g(g_xdh + (size_t)br * BB * LL * 80, g_xdl + (size_t)br * BB * LL * 80, j, s);
}

// =================== dt GEMM: 128x128, K=48, softplus ===================
struct G48B { float* C[2]; const float* bias[2]; };

__global__ void __launch_bounds__(256) gemm_mma48b(G48B g) {
    extern __shared__ char smem[];
    const uint32_t sb = smem_u32(smem);
    const int br = blockIdx.z;
    const uint16_t* __restrict__ Ahp = g_xdh + (size_t)br * BB * LL * 80;
    const uint16_t* __restrict__ Alp = g_xdl + (size_t)br * BB * LL * 80;
    const uint16_t* __restrict__ Bhp = g_dtwh + (size_t)br * DI * DTR;
    const uint16_t* __restrict__ Blp = g_dtwl + (size_t)br * DI * DTR;
    float* __restrict__ C = g.C[br];
    const float* __restrict__ bias = g.bias[br];

    const int tid  = threadIdx.x;
    const int wid  = tid >> 5;
    const int lane = tid & 31;
    const int wm   = wid & 3;
    const int wn   = wid >> 2;
    const int bm = blockIdx.y * 128;
    const int bn = blockIdx.x * 128;

    const uint32_t ah = sb, al = sb + 16384, bh = sb + 32768, bl = sb + 49152;
    const uint4 zz = make_uint4(0, 0, 0, 0);

#pragma unroll
    for (int t = 0; t < 4; t++) {
        int i = tid + t * 256;
        int r = i >> 3, q = i & 7;
        uint32_t off = SWZ128((uint32_t)(r * 128 + q * 16));
        uint4 vh = zz, vl = zz;
        if (q < 6) {
            size_t ao = (size_t)(bm + r) * 80 + q * 8;
            vh = *(const uint4*)(Ahp + ao);
            vl = *(const uint4*)(Alp + ao);
        }
        STS128U(ah + off, vh);
        STS128U(al + off, vl);
        uint4 wh = zz, wl = zz;
        if (q < 6) {
            size_t bo = (size_t)(bn + r) * DTR + q * 8;
            wh = *(const uint4*)(Bhp + bo);
            wl = *(const uint4*)(Blp + bo);
        }
        STS128U(bh + off, wh);
        STS128U(bl + off, wl);
    }
    __syncthreads();

    float acc[2][8][4];
#pragma unroll
    for (int mt = 0; mt < 2; mt++)
#pragma unroll
        for (int nt = 0; nt < 8; nt++)
#pragma unroll
            for (int q = 0; q < 4; q++) acc[mt][nt][q] = 0.f;

    const int a_row = wm * 32 + (lane & 7) + ((lane >> 3) & 1) * 8;
    const int a_kc8 = (lane >> 4) * 8;
    const int b_row = wn * 64 + (lane & 7);
    const int b_kc8 = ((lane >> 3) & 1) * 8;

#pragma unroll
    for (int ks = 0; ks < 3; ks++) {
        const int k0 = ks * 16;
        uint32_t ahi[2][4], alo[2][4];
#pragma unroll
        for (int mt = 0; mt < 2; mt++) {
            uint32_t off = SWZ128((uint32_t)((a_row + mt * 16) * 128 + (k0 + a_kc8) * 2));
            LDSM_X4(ahi[mt][0], ahi[mt][1], ahi[mt][2], ahi[mt][3], ah + off);
            LDSM_X4(alo[mt][0], alo[mt][1], alo[mt][2], alo[mt][3], al + off);
        }
#pragma unroll
        for (int nt = 0; nt < 8; nt++) {
            uint32_t off = SWZ128((uint32_t)((b_row + nt * 8) * 128 + (k0 + b_kc8) * 2));
            uint32_t bhi[2], blo[2];
            LDSM_X2(bhi[0], bhi[1], bh + off);
            LDSM_X2(blo[0], blo[1], bl + off);
#pragma unroll
            for (int mt = 0; mt < 2; mt++) {
                MMA16816(acc[mt][nt], ahi[mt], bhi);
                MMA16816(acc[mt][nt], ahi[mt], blo);
                MMA16816(acc[mt][nt], alo[mt], bhi);
            }
        }
    }

    const int er = lane >> 2;
    const int ec = (lane & 3) * 2;
#pragma unroll
    for (int mt = 0; mt < 2; mt++) {
        const int m = bm + wm * 32 + mt * 16 + er;
#pragma unroll
        for (int nt = 0; nt < 8; nt++) {
            const int n = bn + wn * 64 + nt * 8 + ec;
            const float b0 = bias[n], b1 = bias[n + 1];
            *(float2*)(C + (size_t)m * DI + n) = make_float2(
                softplus_f(acc[mt][nt][0] + b0), softplus_f(acc[mt][nt][1] + b1));
            *(float2*)(C + (size_t)(m + 8) * DI + n) = make_float2(
                softplus_f(acc[mt][nt][2] + b0), softplus_f(acc[mt][nt][3] + b1));
        }
    }
}

// ---------------- depthwise causal conv (K=4) + SiLU + bf16 split output ----------------
__global__ void __launch_bounds__(256)
conv_silu_k(const float* __restrict__ cw0, const float* __restrict__ cb0,
            const float* __restrict__ cw1, const float* __restrict__ cb1) {
    const size_t idx4 = (size_t)blockIdx.x * 256 + threadIdx.x;
    const int D4 = DI / 4;
    if (idx4 >= (size_t)BB * LL * D4) return;
    const int dq = (int)(idx4 % D4);
    const int l  = (int)((idx4 / D4) % LL);
    const int b  = (int)(idx4 / ((size_t)D4 * LL));
    const int d  = dq * 4;

    const float* xzb = g_xz + (size_t)b * LL * 2 * DI + d;

    float w0[4][4], w1[4][4];
#pragma unroll
    for (int j = 0; j < 4; j++) {
        float4 a = *(const float4*)(cw0 + (d + j) * 4);
        w0[j][0] = a.x; w0[j][1] = a.y; w0[j][2] = a.z; w0[j][3] = a.w;
        float4 c = *(const float4*)(cw1 + (d + j) * 4);
        w1[j][0] = c.x; w1[j][1] = c.y; w1[j][2] = c.z; w1[j][3] = c.w;
    }

    float s0[4], s1[4];
    {
        float4 b0 = *(const float4*)(cb0 + d);
        float4 b1 = *(const float4*)(cb1 + d);
        s0[0] = b0.x; s0[1] = b0.y; s0[2] = b0.z; s0[3] = b0.w;
        s1[0] = b1.x; s1[1] = b1.y; s1[2] = b1.z; s1[3] = b1.w;
    }

#pragma unroll
    for (int k = 0; k < 4; k++) {
        const int ls = l - 3 + k;
        if (ls >= 0) {
            float4 xv = *(const float4*)(xzb + (size_t)ls * 2 * DI);
            s0[0] += xv.x * w0[0][k]; s0[1] += xv.y * w0[1][k];
            s0[2] += xv.z * w0[2][k]; s0[3] += xv.w * w0[3][k];
            const int src = LL - 1 - l + 3 - k;
            float4 yv = *(const float4*)(xzb + (size_t)src * 2 * DI);
            s1[0] += yv.x * w1[0][k]; s1[1] += yv.y * w1[1][k];
            s1[2] += yv.z * w1[2][k]; s1[3] += yv.w * w1[3][k];
        }
    }

    float4 o0 = make_float4(silu_f(s0[0]), silu_f(s0[1]), silu_f(s0[2]), silu_f(s0[3]));
    float4 o1 = make_float4(silu_f(s1[0]), silu_f(s1[1]), silu_f(s1[2]), silu_f(s1[3]));
    const size_t o = ((size_t)b * LL + l) * DI + d;
    *(float4*)(g_xc0 + o) = o0;
    *(float4*)(g_xc1 + o) = o1;
    split_g(g_xc0h, g_xc0l, o, o0);
    split_g(g_xc1h, g_xc1l, o, o1);
}

// ---------------- selective scan pass A ----------------
__global__ void __launch_bounds__(128)
scan_passA(const float* __restrict__ AlogF, const float* __restrict__ AlogR) {
    const int tid = threadIdx.x;
    const int d = blockIdx.x * 128 + tid;
    const int seg = blockIdx.y;
    const int b = blockIdx.z & 1;
    const int br = blockIdx.z >> 1;

    const float* Alog   = br ? AlogR   : AlogF;
    const float* gdelta = br ? g_delta1 : g_delta0;
    const float* gxc    = br ? g_xc1    : g_xc0;
    const float* gxdbl  = br ? g_xdbl1  : g_xdbl0;
    float* gP = br ? g_segP1 : g_segP0;
    float* gH = br ? g_segH1 : g_segH0;

    float An[NST];
    bool fast = true;
#pragma unroll
    for (int n = 0; n < NST; n++) {
        An[n] = -__expf(Alog[d * NST + n]);
        if (fabsf(An[n] + (float)(n + 1)) > 1e-3f) fast = false;
    }

    float H[NST], P[NST];
#pragma unroll
    for (int n = 0; n < NST; n++) { H[n] = 0.f; P[n] = 1.f; }

    const size_t rowbase = (size_t)b * LL + (size_t)seg * SEGL;
    const float* dp = gdelta + rowbase * DI + d;
    const float* xp = gxc + rowbase * DI + d;
    const float* bc = gxdbl + rowbase * 80 + 48;

    __shared__ __align__(16) float sBC[32 * 32];
    for (int i = tid; i < 32 * 32; i += 128) {
        int li = i >> 5, c = i & 31;
        sBC[i] = bc[(size_t)li * 80 + c];
    }
    __syncthreads();

#pragma unroll
    for (int l = 0; l < SEGL; l++) {
        const float delta = dp[(size_t)l * DI];
        const float x = xp[(size_t)l * DI];
        const float dx = delta * x;
        float bv[NST];
        const float4* q = (const float4*)&sBC[l * 32];
        ((float4*)bv)[0] = q[0]; ((float4*)bv)[1] = q[1];
        ((float4*)bv)[2] = q[2]; ((float4*)bv)[3] = q[3];
        if (fast) {
            const float e = __expf(-delta);
            float p = 1.f;
#pragma unroll
            for (int n = 0; n < NST; n++) {
                p *= e;
                H[n] = fmaf(p, H[n], dx * bv[n]);
                P[n] *= p;
            }
        } else {
#pragma unroll
            for (int n = 0; n < NST; n++) {
                float da = __expf(delta * An[n]);
                H[n] = fmaf(da, H[n], dx * bv[n]);
                P[n] *= da;
            }
        }
    }

    const size_t o = (((size_t)b * NSEG + seg) * DI + d) * NST;
#pragma unroll
    for (int i = 0; i < 4; i++) {
        ((float4*)&gP[o])[i] = ((float4*)P)[i];
        ((float4*)&gH[o])[i] = ((float4*)H)[i];
    }
}

// ---------------- pass B: combine -> per-segment start states (parallel over n) ----------------
__global__ void __launch_bounds__(128)
scan_passB() {
    const int idx = blockIdx.x * 128 + threadIdx.x;   // BB*2*DI*4 total
    const int ng = idx & 3;
    const int rest = idx >> 2;
    const int d = rest % DI;
    const int rest2 = rest / DI;
    const int b = rest2 & 1;
    const int br = rest2 >> 1;
    float* gP = br ? g_segP1 : g_segP0;
    const float* gH = br ? g_segH1 : g_segH0;

    float4 h = make_float4(0.f, 0.f, 0.f, 0.f);
    for (int t = 0; t < NSEG; t++) {
        const size_t o = (((size_t)b * NSEG + t) * DI + d) * NST + ng * 4;
        float4 P, H;
        if (t < NSEG - 1) {
            P = *(const float4*)&gP[o];
            H = *(const float4*)&gH[o];
        }
        *(float4*)&gP[o] = h;
        if (t < NSEG - 1) {
            h.x = fmaf(P.x, h.x, H.x);
            h.y = fmaf(P.y, h.y, H.y);
            h.z = fmaf(P.z, h.z, H.z);
            h.w = fmaf(P.w, h.w, H.w);
        }
    }
}

// ---------------- pass C rev: rev-branch re-scan -> pre-gate partial (f32, unflipped) ----------------
__global__ void __launch_bounds__(128)
scan_passC_rev(const float* __restrict__ AlogR, const float* __restrict__ Dr) {
    const int tid = threadIdx.x;
    const int d = blockIdx.x * 128 + tid;
    const int seg = blockIdx.y;          // rev-coordinate segment
    const int b = blockIdx.z;

    float An[NST];
    bool fast = true;
#pragma unroll
    for (int n = 0; n < NST; n++) {
        An[n] = -__expf(AlogR[d * NST + n]);
        if (fabsf(An[n] + (float)(n + 1)) > 1e-3f) fast = false;
    }

    float h[NST];
    {
        const size_t o = (((size_t)b * NSEG + seg) * DI + d) * NST;
#pragma unroll
        for (int i = 0; i < 4; i++) ((float4*)h)[i] = ((const float4*)&g_segP1[o])[i];
    }

    const float Dd = Dr[d];
    const size_t rowbase = (size_t)b * LL + (size_t)seg * SEGL;
    const float* dp = g_delta1 + rowbase * DI + d;
    const float* xp = g_xc1 + rowbase * DI + d;
    const float* bc = g_xdbl1 + rowbase * 80 + 48;

    __shared__ __align__(16) float sBC[32 * 32];
    for (int i = tid; i < 32 * 32; i += 128) {
        int li = i >> 5, c = i & 31;
        sBC[i] = bc[(size_t)li * 80 + c];
    }
    __syncthreads();

#pragma unroll
    for (int l = 0; l < SEGL; l++) {
        const float delta = dp[(size_t)l * DI];
        const float x = xp[(size_t)l * DI];
        const float dx = delta * x;
        float bv[NST], cv[NST];
        const float4* q = (const float4*)&sBC[l * 32];
        ((float4*)bv)[0] = q[0]; ((float4*)bv)[1] = q[1];
        ((float4*)bv)[2] = q[2]; ((float4*)bv)[3] = q[3];
        ((float4*)cv)[0] = q[4]; ((float4*)cv)[1] = q[5];
        ((float4*)cv)[2] = q[6]; ((float4*)cv)[3] = q[7];
        float y = 0.f;
        if (fast) {
            const float e = __expf(-delta);
            float p = 1.f;
#pragma unroll
            for (int n = 0; n < NST; n++) {
                p *= e;
                h[n] = fmaf(p, h[n], dx * bv[n]);
                y = fmaf(h[n], cv[n], y);
            }
        } else {
#pragma unroll
            for (int n = 0; n < NST; n++) {
                float da = __expf(delta * An[n]);
                h[n] = fmaf(da, h[n], dx * bv[n]);
                y = fmaf(h[n], cv[n], y);
            }
        }
        const int gl = seg * SEGL + l;
        const int lo = LL - 1 - gl;       // un-flip
        g_ys1[((size_t)b * LL + lo) * DI + d] = y + x * Dd;
    }
}

// ---------------- pass C fwd: fwd re-scan + add rev partial + gate + bf16 split ----------------
__global__ void __launch_bounds__(128)
scan_passC_fwd(const float* __restrict__ AlogF, const float* __restrict__ Df) {
    const int tid = threadIdx.x;
    const int d = blockIdx.x * 128 + tid;
    const int seg = blockIdx.y;
    const int b = blockIdx.z;

    float An[NST];
    bool fast = true;
#pragma unroll
    for (int n = 0; n < NST; n++) {
        An[n] = -__expf(AlogF[d * NST + n]);
        if (fabsf(An[n] + (float)(n + 1)) > 1e-3f) fast = false;
    }

    float h[NST];
    {
        const size_t o = (((size_t)b * NSEG + seg) * DI + d) * NST;
#pragma unroll
        for (int i = 0; i < 4; i++) ((float4*)h)[i] = ((const float4*)&g_segP0[o])[i];
    }

    const float Dd = Df[d];
    const size_t rowbase = (size_t)b * LL + (size_t)seg * SEGL;
    const float* dp = g_delta0 + rowbase * DI + d;
    const float* xp = g_xc0 + rowbase * DI + d;
    const float* bc = g_xdbl0 + rowbase * 80 + 48;
    const float* gz = g_xz + (size_t)b * LL * 2 * DI + DI + d;
    const float* yr = g_ys1 + rowbase * DI + d;

    __shared__ __align__(16) float sBC[32 * 32];
    for (int i = tid; i < 32 * 32; i += 128) {
        int li = i >> 5, c = i & 31;
        sBC[i] = bc[(size_t)li * 80 + c];
    }
    __syncthreads();

#pragma unroll
    for (int l = 0; l < SEGL; l++) {
        const int gl = seg * SEGL + l;
        const float delta = dp[(size_t)l * DI];
        const float x = xp[(size_t)l * DI];
        const float dx = delta * x;
        float bv[NST], cv[NST];
        const float4* q = (const float4*)&sBC[l * 32];
        ((float4*)bv)[0] = q[0]; ((float4*)bv)[1] = q[1];
        ((float4*)bv)[2] = q[2]; ((float4*)bv)[3] = q[3];
        ((float4*)cv)[0] = q[4]; ((float4*)cv)[1] = q[5];
        ((float4*)cv)[2] = q[6]; ((float4*)cv)[3] = q[7];
        float y = 0.f;
        if (fast) {
            const float e = __expf(-delta);
            float p = 1.f;
#pragma unroll
            for (int n = 0; n < NST; n++) {
                p *= e;
                h[n] = fmaf(p, h[n], dx * bv[n]);
                y = fmaf(h[n], cv[n], y);
            }
        } else {
#pragma unroll
            for (int n = 0; n < NST; n++) {
                float da = __expf(delta * An[n]);
                h[n] = fmaf(da, h[n], dx * bv[n]);
                y = fmaf(h[n], cv[n], y);
            }
        }
        const float zv = gz[(size_t)gl * 2 * DI];
        const float out = ((y + x * Dd) + yr[(size_t)l * DI]) * silu_f(zv);
        const size_t o = ((size_t)b * LL + gl) * DI + d;
        __nv_bfloat16 hv = __float2bfloat16(out);
        __nv_bfloat16 lv = __float2bfloat16(out - __bfloat162float(hv));
        g_ysh[o] = *(const uint16_t*)&hv;
        g_ysl[o] = *(const uint16_t*)&lv;
    }
}

// ---------------- launch ----------------
extern "C" void kernel_launch(void* const* d_in, const int* in_sizes, int n_in,
                              void* d_out, int out_size) {
    const float* hidden     = (const float*)d_in[0];
    const float* in_proj_w  = (const float*)d_in[1];
    const float* conv_w     = (const float*)d_in[2];
    const float* conv_b     = (const float*)d_in[3];
    const float* x_proj_w   = (const float*)d_in[4];
    const float* dt_proj_w  = (const float*)d_in[5];
    const float* dt_proj_b  = (const float*)d_in[6];
    const float* A_log      = (const float*)d_in[7];
    const float* Dv         = (const float*)d_in[8];
    const float* conv_w_b   = (const float*)d_in[9];
    const float* conv_b_b   = (const float*)d_in[10];
    const float* x_proj_w_b = (const float*)d_in[11];
    const float* dt_proj_w_b= (const float*)d_in[12];
    const float* dt_proj_b_b= (const float*)d_in[13];
    const float* A_b_log    = (const float*)d_in[14];
    const float* D_b        = (const float*)d_in[15];
    const float* out_proj_w = (const float*)d_in[16];
    float* out = (float*)d_out;

    float *p_xz, *p_delta0, *p_delta1;
    cudaGetSymbolAddress((void**)&p_xz, g_xz);
    cudaGetSymbolAddress((void**)&p_delta0, g_delta0);
    cudaGetSymbolAddress((void**)&p_delta1, g_delta1);
    uint16_t *p_hidh, *p_hidl, *p_w1h, *p_w1l, *p_xwh, *p_xwl, *p_dtwh, *p_dtwl;
    uint16_t *p_owh, *p_owl, *p_xc0h, *p_xc0l, *p_xc1h, *p_xc1l, *p_ysh, *p_ysl;
    cudaGetSymbolAddress((void**)&p_hidh, g_hidh);
    cudaGetSymbolAddress((void**)&p_hidl, g_hidl);
    cudaGetSymbolAddress((void**)&p_w1h, g_w1h);
    cudaGetSymbolAddress((void**)&p_w1l, g_w1l);
    cudaGetSymbolAddress((void**)&p_xwh, g_xwh);
    cudaGetSymbolAddress((void**)&p_xwl, g_xwl);
    cudaGetSymbolAddress((void**)&p_dtwh, g_dtwh);
    cudaGetSymbolAddress((void**)&p_dtwl, g_dtwl);
    cudaGetSymbolAddress((void**)&p_owh, g_owh);
    cudaGetSymbolAddress((void**)&p_owl, g_owl);
    cudaGetSymbolAddress((void**)&p_xc0h, g_xc0h);
    cudaGetSymbolAddress((void**)&p_xc0l, g_xc0l);
    cudaGetSymbolAddress((void**)&p_xc1h, g_xc1h);
    cudaGetSymbolAddress((void**)&p_xc1l, g_xc1l);
    cudaGetSymbolAddress((void**)&p_ysh, g_ysh);
    cudaGetSymbolAddress((void**)&p_ysl, g_ysl);

    cudaFuncSetAttribute(gemm_mma_s<128>, cudaFuncAttributeMaxDynamicSharedMemorySize, 65536);
    cudaFuncSetAttribute(gemm_mma_s<64>,  cudaFuncAttributeMaxDynamicSharedMemorySize, 49152);
    cudaFuncSetAttribute(gemm_mma80b, cudaFuncAttributeMaxDynamicSharedMemorySize, MMA80_SMEM);
    cudaFuncSetAttribute(gemm_mma48b, cudaFuncAttributeMaxDynamicSharedMemorySize, 65536);

    const int M = BB * LL;  // 2048

    // 0) pre-split static tensors to bf16 hi/lo
    {
        SArgs sa{};
        int base = 0;
        auto add = [&](int k, const float* src, uint16_t* hi, uint16_t* lo, int n) {
            sa.s[k] = SSeg{src, hi, lo, base, n / 4};
            base += n / 4;
        };
        add(0, hidden,      p_hidh, p_hidl, M * DM);
        add(1, in_proj_w,   p_w1h,  p_w1l,  2 * DI * DM);
        add(2, x_proj_w,    p_xwh,            p_xwl,            80 * DI);
        add(3, x_proj_w_b,  p_xwh + 80 * DI,  p_xwl + 80 * DI,  80 * DI);
        add(4, dt_proj_w,   p_dtwh,           p_dtwl,           DI * DTR);
        add(5, dt_proj_w_b, p_dtwh + DI * DTR,p_dtwl + DI * DTR,DI * DTR);
        add(6, out_proj_w,  p_owh,  p_owl,  DM * DI);
        sa.total4 = base;
        split_many<<<(base + 255) / 256, 256>>>(sa);
    }

    // 1) xz = hidden @ in_proj_w^T
    {
        TBArgs a{};
        a.Ah = p_hidh; a.Al = p_hidl; a.Bh = p_w1h; a.Bl = p_w1l; a.C = p_xz;
        a.K = DM; a.lda = DM; a.ldb = DM; a.ldc = 2 * DI;
        gemm_mma_s<128><<<dim3(2 * DI / 128, M / 128), 256, 65536>>>(a);
    }

    // 2) conv + silu (+ bf16 split of xc)
    conv_silu_k<<<(unsigned)(((size_t)M * (DI / 4) + 255) / 256), 256>>>(
        conv_w, conv_b, conv_w_b, conv_b_b);

    // 3) x_dbl partials (split-K 4), both branches
    {
        G80B a{};
        a.Ah[0] = p_xc0h; a.Ah[1] = p_xc1h;
        a.Al[0] = p_xc0l; a.Al[1] = p_xc1l;
        gemm_mma80b<<<dim3(1, M / 64, 8), 256, MMA80_SMEM>>>(a);
    }

    // 4) combine partials -> f32 xdbl + bf16 split
    xdbl_combine<<<(2 * (M * 80 / 4) + 255) / 256, 256>>>();

    // 5) delta = softplus(dt @ dt_proj_w^T + bias)
    {
        G48B a{};
        a.C[0] = p_delta0; a.C[1] = p_delta1;
        a.bias[0] = dt_proj_b; a.bias[1] = dt_proj_b_b;
        gemm_mma48b<<<dim3(DI / 128, M / 128, 2), 256, 65536>>>(a);
    }

    // 6) scan pass A (segments 0..NSEG-2, both branches)
    scan_passA<<<dim3(DI / 128, NSEG - 1, 4), 128>>>(A_log, A_b_log);

    // 7) pass B: per-segment start states (parallel over state dim)
    scan_passB<<<(BB * 2 * DI * 4) / 128, 128>>>();

    // 8) pass C rev: rev branch -> f32 pre-gate partial at unflipped locations
    scan_passC_rev<<<dim3(DI / 128, NSEG, BB), 128>>>(A_b_log, D_b);

    // 9) pass C fwd: fwd branch + add rev partial + gate + bf16 split
    scan_passC_fwd<<<dim3(DI / 128, NSEG, BB), 128>>>(A_log, Dv);

    // 10) out = ysum @ out_proj_w^T
    {
        TBArgs a{};
        a.Ah = p_ysh; a.Al = p_ysl; a.Bh = p_owh; a.Bl = p_owl; a.C = out;
        a.K = DI; a.lda = DI; a.ldb = DI; a.ldc = DM;
        gemm_mma_s<64><<<dim3(DM / 64, M / 128), 256, 49152>>>(a);
    }
}

// round 15
// speedup vs baseline: 1.0747x; 1.0747x over previous
#include <cuda_runtime.h>
#include <cuda_bf16.h>
#include <math.h>
#include <stdint.h>

#define DI   1536
#define DM   768
#define NST  16
#define DTR  48
#define BB   2
#define LL   1024
#define NSEG 32
#define SEGL (LL / NSEG)

// ---------------- scratch (device globals; no allocation allowed) ----------------
__device__ float g_xz[(size_t)BB * LL * 2 * DI];      // in_proj output (x | z)
__device__ float g_xc0[(size_t)BB * LL * DI];         // conv+silu fwd (f32, for scans)
__device__ float g_xc1[(size_t)BB * LL * DI];
__device__ float g_xdbl0[(size_t)BB * LL * 80];       // x_proj out (summed): [dt|B|C]
__device__ float g_xdbl1[(size_t)BB * LL * 80];
__device__ float g_delta0[(size_t)BB * LL * DI];
__device__ float g_delta1[(size_t)BB * LL * DI];
__device__ float g_segP0[(size_t)BB * NSEG * DI * NST];
__device__ float g_segP1[(size_t)BB * NSEG * DI * NST];
__device__ float g_segH0[(size_t)BB * NSEG * DI * NST];
__device__ float g_segH1[(size_t)BB * NSEG * DI * NST];
__device__ float g_ys0[(size_t)BB * LL * DI];
__device__ float g_ys1[(size_t)BB * LL * DI];
__device__ float g_xdblp[(size_t)8 * BB * LL * 80];   // x_proj partials [br*4+kq]

// bf16 hi/lo pre-split buffers
__device__ uint16_t g_hidh[(size_t)BB * LL * DM],     g_hidl[(size_t)BB * LL * DM];
__device__ uint16_t g_w1h[(size_t)2 * DI * DM],       g_w1l[(size_t)2 * DI * DM];
__device__ uint16_t g_xc0h[(size_t)BB * LL * DI],     g_xc0l[(size_t)BB * LL * DI];
__device__ uint16_t g_xc1h[(size_t)BB * LL * DI],     g_xc1l[(size_t)BB * LL * DI];
__device__ uint16_t g_xwh[(size_t)2 * 80 * DI],       g_xwl[(size_t)2 * 80 * DI];
__device__ uint16_t g_dtwh[(size_t)2 * DI * DTR],     g_dtwl[(size_t)2 * DI * DTR];
__device__ uint16_t g_owh[(size_t)DM * DI],           g_owl[(size_t)DM * DI];
__device__ uint16_t g_xdh[(size_t)2 * BB * LL * 80],  g_xdl[(size_t)2 * BB * LL * 80];
__device__ uint16_t g_ysh[(size_t)BB * LL * DI],      g_ysl[(size_t)BB * LL * DI];

// =================== helpers ===================
__device__ __forceinline__ uint32_t smem_u32(const void* p) {
    uint32_t a;
    asm("{ .reg .u64 t; cvta.to.shared.u64 t, %1; cvt.u32.u64 %0, t; }" : "=r"(a) : "l"(p));
    return a;
}
#define SWZ128(x) ((x) ^ (((x) >> 3) & 0x70))

__device__ __forceinline__ void split2(float a0, float a1, uint32_t& hi, uint32_t& lo) {
    asm("cvt.rn.bf16x2.f32 %0, %1, %2;" : "=r"(hi) : "f"(a1), "f"(a0));
    float h0 = __uint_as_float(hi << 16);
    float h1 = __uint_as_float(hi & 0xffff0000u);
    float r0 = a0 - h0, r1 = a1 - h1;
    asm("cvt.rn.bf16x2.f32 %0, %1, %2;" : "=r"(lo) : "f"(r1), "f"(r0));
}

__device__ __forceinline__ void split_g(uint16_t* hi, uint16_t* lo, size_t j, float4 v) {
    uint32_t h01, l01, h23, l23;
    split2(v.x, v.y, h01, l01);
    split2(v.z, v.w, h23, l23);
    *(uint2*)(hi + j) = make_uint2(h01, h23);
    *(uint2*)(lo + j) = make_uint2(l01, l23);
}

#define LDSM_X4(r0, r1, r2, r3, a) \
    asm volatile("ldmatrix.sync.aligned.m8n8.x4.shared.b16 {%0,%1,%2,%3}, [%4];" \
                 : "=r"(r0), "=r"(r1), "=r"(r2), "=r"(r3) : "r"(a))
#define LDSM_X2(r0, r1, a) \
    asm volatile("ldmatrix.sync.aligned.m8n8.x2.shared.b16 {%0,%1}, [%2];" \
                 : "=r"(r0), "=r"(r1) : "r"(a))
#define MMA16816(c, a, b) \
    asm volatile("mma.sync.aligned.m16n8k16.row.col.f32.bf16.bf16.f32 " \
                 "{%0,%1,%2,%3}, {%4,%5,%6,%7}, {%8,%9}, {%0,%1,%2,%3};" \
                 : "+f"((c)[0]), "+f"((c)[1]), "+f"((c)[2]), "+f"((c)[3]) \
                 : "r"((a)[0]), "r"((a)[1]), "r"((a)[2]), "r"((a)[3]), \
                   "r"((b)[0]), "r"((b)[1]))
#define STS128U(addr, v) \
    asm volatile("st.shared.v4.b32 [%0], {%1,%2,%3,%4};" \
                 :: "r"(addr), "r"((v).x), "r"((v).y), "r"((v).z), "r"((v).w) : "memory")

__device__ __forceinline__ float silu_f(float v) {
    return v / (1.f + __expf(-v));
}
__device__ __forceinline__ float softplus_f(float v) {
    return fmaxf(v, 0.f) + __logf(1.f + __expf(-fabsf(v)));
}

// =================== split_many: pre-split static tensors ===================
struct SSeg { const float* src; uint16_t* hi; uint16_t* lo; int base4; int n4; };
struct SArgs { SSeg s[7]; int total4; };

__global__ void __launch_bounds__(256) split_many(SArgs a) {
    int idx = blockIdx.x * 256 + threadIdx.x;
    if (idx >= a.total4) return;
#pragma unroll
    for (int k = 0; k < 7; k++) {
        int j = idx - a.s[k].base4;
        if (j >= 0 && j < a.s[k].n4) {
            float4 v = *(const float4*)(a.s[k].src + (size_t)j * 4);
            split_g(a.s[k].hi, a.s[k].lo, (size_t)j * 4, v);
            return;
        }
    }
}

// =================== NT GEMM 128xBN (bf16 pre-split, single-buffer pipeline) ===================
struct TBArgs {
    const uint16_t* Ah; const uint16_t* Al;
    const uint16_t* Bh; const uint16_t* Bl;
    float* C; int K, lda, ldb, ldc;
};

template <int BN>
__global__ void __launch_bounds__(256) gemm_mma_s(TBArgs g) {
    extern __shared__ char smem[];
    const uint32_t sb = smem_u32(smem);
    constexpr int NT = BN / 16;
    constexpr int BHOFF = 32768;
    constexpr int BLOFF = 32768 + BN * 128;
    constexpr int BITER = (BN * 8) / 256;

    const int tid  = threadIdx.x;
    const int wid  = tid >> 5;
    const int lane = tid & 31;
    const int wm   = wid & 3;
    const int wn   = wid >> 2;
    const int bm = blockIdx.y * 128;
    const int bn = blockIdx.x * BN;

    uint4 rah[4], ral[4], rbh[BITER], rbl[BITER];
    float acc[2][NT][4];
#pragma unroll
    for (int mt = 0; mt < 2; mt++)
#pragma unroll
        for (int nt = 0; nt < NT; nt++)
#pragma unroll
            for (int q = 0; q < 4; q++) acc[mt][nt][q] = 0.f;

    auto ldg_tile = [&](int k0) {
#pragma unroll
        for (int t = 0; t < 4; t++) {
            int i = tid + t * 256;
            int r = i >> 3, q = i & 7;
            size_t ao = (size_t)(bm + r) * g.lda + k0 + q * 8;
            rah[t] = *(const uint4*)(g.Ah + ao);
            ral[t] = *(const uint4*)(g.Al + ao);
        }
#pragma unroll
        for (int t = 0; t < BITER; t++) {
            int i = tid + t * 256;
            int r = i >> 3, q = i & 7;
            size_t bo = (size_t)(bn + r) * g.ldb + k0 + q * 8;
            rbh[t] = *(const uint4*)(g.Bh + bo);
            rbl[t] = *(const uint4*)(g.Bl + bo);
        }
    };
    auto sts_tile = [&]() {
#pragma unroll
        for (int t = 0; t < 4; t++) {
            int i = tid + t * 256;
            int r = i >> 3, q = i & 7;
            uint32_t off = SWZ128((uint32_t)(r * 128 + q * 16));
            STS128U(sb + off, rah[t]);
            STS128U(sb + 16384 + off, ral[t]);
        }
#pragma unroll
        for (int t = 0; t < BITER; t++) {
            int i = tid + t * 256;
            int r = i >> 3, q = i & 7;
            uint32_t off = SWZ128((uint32_t)(r * 128 + q * 16));
            STS128U(sb + BHOFF + off, rbh[t]);
            STS128U(sb + BLOFF + off, rbl[t]);
        }
    };

    const int a_row = wm * 32 + (lane & 7) + ((lane >> 3) & 1) * 8;
    const int a_kc8 = (lane >> 4) * 8;
    const int b_row = wn * (BN / 2) + (lane & 7);
    const int b_kc8 = ((lane >> 3) & 1) * 8;

    auto compute = [&]() {
#pragma unroll
        for (int ks = 0; ks < 4; ks++) {
            const int k0 = ks * 16;
            uint32_t ahi[2][4], alo[2][4];
#pragma unroll
            for (int mt = 0; mt < 2; mt++) {
                uint32_t off = SWZ128((uint32_t)((a_row + mt * 16) * 128 + (k0 + a_kc8) * 2));
                LDSM_X4(ahi[mt][0], ahi[mt][1], ahi[mt][2], ahi[mt][3], sb + off);
                LDSM_X4(alo[mt][0], alo[mt][1], alo[mt][2], alo[mt][3], sb + 16384 + off);
            }
#pragma unroll
            for (int nt = 0; nt < NT; nt++) {
                uint32_t off = SWZ128((uint32_t)((b_row + nt * 8) * 128 + (k0 + b_kc8) * 2));
                uint32_t bhi[2], blo[2];
                LDSM_X2(bhi[0], bhi[1], sb + BHOFF + off);
                LDSM_X2(blo[0], blo[1], sb + BLOFF + off);
#pragma unroll
                for (int mt = 0; mt < 2; mt++) {
                    MMA16816(acc[mt][nt], ahi[mt], bhi);
                    MMA16816(acc[mt][nt], ahi[mt], blo);
                    MMA16816(acc[mt][nt], alo[mt], bhi);
                }
            }
        }
    };

    const int nk = g.K >> 6;
    ldg_tile(0);
    sts_tile();
    __syncthreads();
    for (int kt = 1; kt < nk; kt++) {
        ldg_tile(kt << 6);        // LDG latency overlapped with compute below
        compute();
        __syncthreads();          // everyone done reading smem
        sts_tile();
        __syncthreads();          // new tile visible
    }
    compute();

    const int er = lane >> 2;
    const int ec = (lane & 3) * 2;
#pragma unroll
    for (int mt = 0; mt < 2; mt++) {
        const int m = bm + wm * 32 + mt * 16 + er;
#pragma unroll
        for (int nt = 0; nt < NT; nt++) {
            const int n = bn + wn * (BN / 2) + nt * 8 + ec;
            *(float2*)(g.C + (size_t)m * g.ldc + n) =
                make_float2(acc[mt][nt][0], acc[mt][nt][1]);
            *(float2*)(g.C + (size_t)(m + 8) * g.ldc + n) =
                make_float2(acc[mt][nt][2], acc[mt][nt][3]);
        }
    }
}

// =================== x_proj GEMM: BM=64, split-K(4), single buffer ===================
struct G80B { const uint16_t* Ah[2]; const uint16_t* Al[2]; };

#define MMA80_SMEM 36864

__global__ void __launch_bounds__(256) gemm_mma80b(G80B g) {
    extern __shared__ char smem[];
    const uint32_t sb = smem_u32(smem);
    const int br = blockIdx.z >> 2;
    const int kq = blockIdx.z & 3;
    const uint16_t* __restrict__ Ah = g.Ah[br];
    const uint16_t* __restrict__ Al = g.Al[br];
    const uint16_t* __restrict__ Bh = g_xwh + (size_t)br * 80 * DI;
    const uint16_t* __restrict__ Bl = g_xwl + (size_t)br * 80 * DI;
    float* __restrict__ C = g_xdblp + (size_t)(br * 4 + kq) * BB * LL * 80;

    const int tid  = threadIdx.x;
    const int wid  = tid >> 5;
    const int lane = tid & 31;
    const int wm   = wid & 3;
    const int wn   = wid >> 2;
    const int bm = blockIdx.y * 64;
    const int kbase = kq * 384;

    uint4 rah[2], ral[2], rbh[3], rbl[3];
    float acc[5][4];
#pragma unroll
    for (int nt = 0; nt < 5; nt++)
#pragma unroll
        for (int q = 0; q < 4; q++) acc[nt][q] = 0.f;

    auto ldg_tile = [&](int k0) {
#pragma unroll
        for (int t = 0; t < 2; t++) {
            int i = tid + t * 256;
            int r = i >> 3, q = i & 7;
            size_t ao = (size_t)(bm + r) * DI + k0 + q * 8;
            rah[t] = *(const uint4*)(Ah + ao);
            ral[t] = *(const uint4*)(Al + ao);
        }
#pragma unroll
        for (int t = 0; t < 3; t++) {
            int i = tid + t * 256;
            if (i < 640) {
                int r = i >> 3, q = i & 7;
                size_t bo = (size_t)r * DI + k0 + q * 8;
                rbh[t] = *(const uint4*)(Bh + bo);
                rbl[t] = *(const uint4*)(Bl + bo);
            }
        }
    };
    auto sts_tile = [&]() {
#pragma unroll
        for (int t = 0; t < 2; t++) {
            int i = tid + t * 256;
            int r = i >> 3, q = i & 7;
            uint32_t off = SWZ128((uint32_t)(r * 128 + q * 16));
            STS128U(sb + off, rah[t]);
            STS128U(sb + 8192 + off, ral[t]);
        }
#pragma unroll
        for (int t = 0; t < 3; t++) {
            int i = tid + t * 256;
            if (i < 640) {
                int r = i >> 3, q = i & 7;
                uint32_t off = SWZ128((uint32_t)(r * 128 + q * 16));
                STS128U(sb + 16384 + off, rbh[t]);
                STS128U(sb + 26624 + off, rbl[t]);
            }
        }
    };

    const int a_row = wm * 16 + (lane & 7) + ((lane >> 3) & 1) * 8;
    const int a_kc8 = (lane >> 4) * 8;
    const int b_row = wn * 40 + (lane & 7);
    const int b_kc8 = ((lane >> 3) & 1) * 8;

    auto compute = [&]() {
#pragma unroll
        for (int ks = 0; ks < 4; ks++) {
            const int k0 = ks * 16;
            uint32_t ahi[4], alo[4];
            {
                uint32_t off = SWZ128((uint32_t)(a_row * 128 + (k0 + a_kc8) * 2));
                LDSM_X4(ahi[0], ahi[1], ahi[2], ahi[3], sb + off);
                LDSM_X4(alo[0], alo[1], alo[2], alo[3], sb + 8192 + off);
            }
#pragma unroll
            for (int nt = 0; nt < 5; nt++) {
                uint32_t off = SWZ128((uint32_t)((b_row + nt * 8) * 128 + (k0 + b_kc8) * 2));
                uint32_t bhi[2], blo[2];
                LDSM_X2(bhi[0], bhi[1], sb + 16384 + off);
                LDSM_X2(blo[0], blo[1], sb + 26624 + off);
                MMA16816(acc[nt], ahi, bhi);
                MMA16816(acc[nt], ahi, blo);
                MMA16816(acc[nt], alo, bhi);
            }
        }
    };

    const int nk = 384 >> 6;
    ldg_tile(kbase);
    sts_tile();
    __syncthreads();
    for (int kt = 1; kt < nk; kt++) {
        ldg_tile(kbase + (kt << 6));
        compute();
        __syncthreads();
        sts_tile();
        __syncthreads();
    }
    compute();

    const int er = lane >> 2;
    const int ec = (lane & 3) * 2;
    const int m = bm + wm * 16 + er;
#pragma unroll
    for (int nt = 0; nt < 5; nt++) {
        const int n = wn * 40 + nt * 8 + ec;
        *(float2*)(C + (size_t)m * 80 + n) = make_float2(acc[nt][0], acc[nt][1]);
        *(float2*)(C + (size_t)(m + 8) * 80 + n) = make_float2(acc[nt][2], acc[nt][3]);
    }
}

// =================== xdbl combine: sum 4 split-K partials -> f32 + bf16 split ===================
__global__ void __launch_bounds__(256) xdbl_combine() {
    const int n4 = (BB * LL * 80) / 4;
    int idx = blockIdx.x * 256 + threadIdx.x;
    if (idx >= 2 * n4) return;
    int br = idx >= n4;
    size_t j = (size_t)(idx - br * n4) * 4;
    float4 s = make_float4(0.f, 0.f, 0.f, 0.f);
#pragma unroll
    for (int k = 0; k < 4; k++) {
        float4 a = *(const float4*)(g_xdblp + (size_t)(br * 4 + k) * BB * LL * 80 + j);
        s.x += a.x; s.y += a.y; s.z += a.z; s.w += a.w;
    }
    float* dst = br ? g_xdbl1 : g_xdbl0;
    *(float4*)(dst + j) = s;
    split_g(g_xdh + (size_t)br * BB * LL * 80, g_xdl + (size_t)br * BB * LL * 80, j, s);
}

// =================== dt GEMM: 128x128, K=48, bf16 pre-split, softplus ===================
struct G48B { float* C[2]; const float* bias[2]; };

__global__ void __launch_bounds__(256) gemm_mma48b(G48B g) {
    extern __shared__ char smem[];
    const uint32_t sb = smem_u32(smem);
    const int br = blockIdx.z;
    const uint16_t* __restrict__ Ahp = g_xdh + (size_t)br * BB * LL * 80;
    const uint16_t* __restrict__ Alp = g_xdl + (size_t)br * BB * LL * 80;
    const uint16_t* __restrict__ Bhp = g_dtwh + (size_t)br * DI * DTR;
    const uint16_t* __restrict__ Blp = g_dtwl + (size_t)br * DI * DTR;
    float* __restrict__ C = g.C[br];
    const float* __restrict__ bias = g.bias[br];

    const int tid  = threadIdx.x;
    const int wid  = tid >> 5;
    const int lane = tid & 31;
    const int wm   = wid & 3;
    const int wn   = wid >> 2;
    const int bm = blockIdx.y * 128;
    const int bn = blockIdx.x * 128;

    const uint32_t ah = sb, al = sb + 16384, bh = sb + 32768, bl = sb + 49152;
    const uint4 zz = make_uint4(0, 0, 0, 0);

#pragma unroll
    for (int t = 0; t < 4; t++) {
        int i = tid + t * 256;
        int r = i >> 3, q = i & 7;
        uint32_t off = SWZ128((uint32_t)(r * 128 + q * 16));
        uint4 vh = zz, vl = zz;
        if (q < 6) {
            size_t ao = (size_t)(bm + r) * 80 + q * 8;
            vh = *(const uint4*)(Ahp + ao);
            vl = *(const uint4*)(Alp + ao);
        }
        STS128U(ah + off, vh);
        STS128U(al + off, vl);
        uint4 wh = zz, wl = zz;
        if (q < 6) {
            size_t bo = (size_t)(bn + r) * DTR + q * 8;
            wh = *(const uint4*)(Bhp + bo);
            wl = *(const uint4*)(Blp + bo);
        }
        STS128U(bh + off, wh);
        STS128U(bl + off, wl);
    }
    __syncthreads();

    float acc[2][8][4];
#pragma unroll
    for (int mt = 0; mt < 2; mt++)
#pragma unroll
        for (int nt = 0; nt < 8; nt++)
#pragma unroll
            for (int q = 0; q < 4; q++) acc[mt][nt][q] = 0.f;

    const int a_row = wm * 32 + (lane & 7) + ((lane >> 3) & 1) * 8;
    const int a_kc8 = (lane >> 4) * 8;
    const int b_row = wn * 64 + (lane & 7);
    const int b_kc8 = ((lane >> 3) & 1) * 8;

#pragma unroll
    for (int ks = 0; ks < 3; ks++) {
        const int k0 = ks * 16;
        uint32_t ahi[2][4], alo[2][4];
#pragma unroll
        for (int mt = 0; mt < 2; mt++) {
            uint32_t off = SWZ128((uint32_t)((a_row + mt * 16) * 128 + (k0 + a_kc8) * 2));
            LDSM_X4(ahi[mt][0], ahi[mt][1], ahi[mt][2], ahi[mt][3], ah + off);
            LDSM_X4(alo[mt][0], alo[mt][1], alo[mt][2], alo[mt][3], al + off);
        }
#pragma unroll
        for (int nt = 0; nt < 8; nt++) {
            uint32_t off = SWZ128((uint32_t)((b_row + nt * 8) * 128 + (k0 + b_kc8) * 2));
            uint32_t bhi[2], blo[2];
            LDSM_X2(bhi[0], bhi[1], bh + off);
            LDSM_X2(blo[0], blo[1], bl + off);
#pragma unroll
            for (int mt = 0; mt < 2; mt++) {
                MMA16816(acc[mt][nt], ahi[mt], bhi);
                MMA16816(acc[mt][nt], ahi[mt], blo);
                MMA16816(acc[mt][nt], alo[mt], bhi);
            }
        }
    }

    const int er = lane >> 2;
    const int ec = (lane & 3) * 2;
#pragma unroll
    for (int mt = 0; mt < 2; mt++) {
        const int m = bm + wm * 32 + mt * 16 + er;
#pragma unroll
        for (int nt = 0; nt < 8; nt++) {
            const int n = bn + wn * 64 + nt * 8 + ec;
            const float b0 = bias[n], b1 = bias[n + 1];
            *(float2*)(C + (size_t)m * DI + n) = make_float2(
                softplus_f(acc[mt][nt][0] + b0), softplus_f(acc[mt][nt][1] + b1));
            *(float2*)(C + (size_t)(m + 8) * DI + n) = make_float2(
                softplus_f(acc[mt][nt][2] + b0), softplus_f(acc[mt][nt][3] + b1));
        }
    }
}

// ---------------- depthwise causal conv (K=4) + SiLU + bf16 split output ----------------
__global__ void __launch_bounds__(256)
conv_silu_k(const float* __restrict__ cw0, const float* __restrict__ cb0,
            const float* __restrict__ cw1, const float* __restrict__ cb1) {
    const size_t idx4 = (size_t)blockIdx.x * 256 + threadIdx.x;
    const int D4 = DI / 4;
    if (idx4 >= (size_t)BB * LL * D4) return;
    const int dq = (int)(idx4 % D4);
    const int l  = (int)((idx4 / D4) % LL);
    const int b  = (int)(idx4 / ((size_t)D4 * LL));
    const int d  = dq * 4;

    const float* xzb = g_xz + (size_t)b * LL * 2 * DI + d;

    float w0[4][4], w1[4][4];
#pragma unroll
    for (int j = 0; j < 4; j++) {
        float4 a = *(const float4*)(cw0 + (d + j) * 4);
        w0[j][0] = a.x; w0[j][1] = a.y; w0[j][2] = a.z; w0[j][3] = a.w;
        float4 c = *(const float4*)(cw1 + (d + j) * 4);
        w1[j][0] = c.x; w1[j][1] = c.y; w1[j][2] = c.z; w1[j][3] = c.w;
    }

    float s0[4], s1[4];
    {
        float4 b0 = *(const float4*)(cb0 + d);
        float4 b1 = *(const float4*)(cb1 + d);
        s0[0] = b0.x; s0[1] = b0.y; s0[2] = b0.z; s0[3] = b0.w;
        s1[0] = b1.x; s1[1] = b1.y; s1[2] = b1.z; s1[3] = b1.w;
    }

#pragma unroll
    for (int k = 0; k < 4; k++) {
        const int ls = l - 3 + k;
        if (ls >= 0) {
            float4 xv = *(const float4*)(xzb + (size_t)ls * 2 * DI);
            s0[0] += xv.x * w0[0][k]; s0[1] += xv.y * w0[1][k];
            s0[2] += xv.z * w0[2][k]; s0[3] += xv.w * w0[3][k];
            const int src = LL - 1 - l + 3 - k;
            float4 yv = *(const float4*)(xzb + (size_t)src * 2 * DI);
            s1[0] += yv.x * w1[0][k]; s1[1] += yv.y * w1[1][k];
            s1[2] += yv.z * w1[2][k]; s1[3] += yv.w * w1[3][k];
        }
    }

    float4 o0 = make_float4(silu_f(s0[0]), silu_f(s0[1]), silu_f(s0[2]), silu_f(s0[3]));
    float4 o1 = make_float4(silu_f(s1[0]), silu_f(s1[1]), silu_f(s1[2]), silu_f(s1[3]));
    const size_t o = ((size_t)b * LL + l) * DI + d;
    *(float4*)(g_xc0 + o) = o0;
    *(float4*)(g_xc1 + o) = o1;
    split_g(g_xc0h, g_xc0l, o, o0);
    split_g(g_xc1h, g_xc1l, o, o1);
}

// ---------------- ys combine: sum branches -> bf16 split ----------------
__global__ void __launch_bounds__(256) ys_split() {
    const size_t n4 = (size_t)BB * LL * DI / 4;
    size_t idx = (size_t)blockIdx.x * 256 + threadIdx.x;
    if (idx >= n4) return;
    size_t j = idx * 4;
    float4 a = *(const float4*)(g_ys0 + j);
    float4 b = *(const float4*)(g_ys1 + j);
    float4 s = make_float4(a.x + b.x, a.y + b.y, a.z + b.z, a.w + b.w);
    split_g(g_ysh, g_ysl, j, s);
}

// ---------------- selective scan pass A ----------------
__global__ void __launch_bounds__(128)
scan_passA(const float* __restrict__ AlogF, const float* __restrict__ AlogR) {
    const int tid = threadIdx.x;
    const int d = blockIdx.x * 128 + tid;
    const int seg = blockIdx.y;
    const int b = blockIdx.z & 1;
    const int br = blockIdx.z >> 1;

    const float* Alog   = br ? AlogR   : AlogF;
    const float* gdelta = br ? g_delta1 : g_delta0;
    const float* gxc    = br ? g_xc1    : g_xc0;
    const float* gxdbl  = br ? g_xdbl1  : g_xdbl0;
    float* gP = br ? g_segP1 : g_segP0;
    float* gH = br ? g_segH1 : g_segH0;

    float An[NST];
    bool fast = true;
#pragma unroll
    for (int n = 0; n < NST; n++) {
        An[n] = -__expf(Alog[d * NST + n]);
        if (fabsf(An[n] + (float)(n + 1)) > 1e-3f) fast = false;
    }

    float H[NST], P[NST];
#pragma unroll
    for (int n = 0; n < NST; n++) { H[n] = 0.f; P[n] = 1.f; }

    const size_t rowbase = (size_t)b * LL + (size_t)seg * SEGL;
    const float* dp = gdelta + rowbase * DI + d;
    const float* xp = gxc + rowbase * DI + d;
    const float* bc = gxdbl + rowbase * 80 + 48;

    __shared__ __align__(16) float sBC[32 * 32];

    for (int lc = 0; lc < SEGL; lc += 32) {
        __syncthreads();
        for (int i = tid; i < 32 * 32; i += 128) {
            int li = i >> 5, c = i & 31;
            sBC[i] = bc[(size_t)(lc + li) * 80 + c];
        }
        __syncthreads();
        for (int li = 0; li < 32; li++) {
            const int l = lc + li;
            const float delta = dp[(size_t)l * DI];
            const float x = xp[(size_t)l * DI];
            const float dx = delta * x;
            float bv[NST];
            const float4* q = (const float4*)&sBC[li * 32];
            ((float4*)bv)[0] = q[0]; ((float4*)bv)[1] = q[1];
            ((float4*)bv)[2] = q[2]; ((float4*)bv)[3] = q[3];
            if (fast) {
                const float e = __expf(-delta);
                float p = 1.f;
#pragma unroll
                for (int n = 0; n < NST; n++) {
                    p *= e;
                    H[n] = fmaf(p, H[n], dx * bv[n]);
                    P[n] *= p;
                }
            } else {
#pragma unroll
                for (int n = 0; n < NST; n++) {
                    float da = __expf(delta * An[n]);
                    H[n] = fmaf(da, H[n], dx * bv[n]);
                    P[n] *= da;
                }
            }
        }
    }

    const size_t o = (((size_t)b * NSEG + seg) * DI + d) * NST;
#pragma unroll
    for (int i = 0; i < 4; i++) {
        ((float4*)&gP[o])[i] = ((float4*)P)[i];
        ((float4*)&gH[o])[i] = ((float4*)H)[i];
    }
}

// ---------------- pass B: combine -> per-segment start states (parallel over n) ----------------
__global__ void __launch_bounds__(128)
scan_passB() {
    const int idx = blockIdx.x * 128 + threadIdx.x;   // BB*2*DI*4 total
    const int ng = idx & 3;
    const int rest = idx >> 2;
    const int d = rest % DI;
    const int rest2 = rest / DI;
    const int b = rest2 & 1;
    const int br = rest2 >> 1;
    float* gP = br ? g_segP1 : g_segP0;
    const float* gH = br ? g_segH1 : g_segH0;

    float4 h = make_float4(0.f, 0.f, 0.f, 0.f);
    for (int t = 0; t < NSEG; t++) {
        const size_t o = (((size_t)b * NSEG + t) * DI + d) * NST + ng * 4;
        float4 P, H;
        if (t < NSEG - 1) {
            P = *(const float4*)&gP[o];
            H = *(const float4*)&gH[o];
        }
        *(float4*)&gP[o] = h;
        if (t < NSEG - 1) {
            h.x = fmaf(P.x, h.x, H.x);
            h.y = fmaf(P.y, h.y, H.y);
            h.z = fmaf(P.z, h.z, H.z);
            h.w = fmaf(P.w, h.w, H.w);
        }
    }
}

// ---------------- pass C: re-scan from start state, emit gated output (both branches parallel) ----------------
__global__ void __launch_bounds__(128)
scan_passC(const float* __restrict__ AlogF, const float* __restrict__ AlogR,
           const float* __restrict__ Df, const float* __restrict__ Dr) {
    const int tid = threadIdx.x;
    const int d = blockIdx.x * 128 + tid;
    const int seg = blockIdx.y;
    const int b = blockIdx.z & 1;
    const int br = blockIdx.z >> 1;

    const float* Alog   = br ? AlogR   : AlogF;
    const float* gdelta = br ? g_delta1 : g_delta0;
    const float* gxc    = br ? g_xc1    : g_xc0;
    const float* gxdbl  = br ? g_xdbl1  : g_xdbl0;
    const float* gS = br ? g_segP1 : g_segP0;
    float* ys = br ? g_ys1 : g_ys0;

    float An[NST];
    bool fast = true;
#pragma unroll
    for (int n = 0; n < NST; n++) {
        An[n] = -__expf(Alog[d * NST + n]);
        if (fabsf(An[n] + (float)(n + 1)) > 1e-3f) fast = false;
    }

    float h[NST];
    {
        const size_t o = (((size_t)b * NSEG + seg) * DI + d) * NST;
#pragma unroll
        for (int i = 0; i < 4; i++) ((float4*)h)[i] = ((const float4*)&gS[o])[i];
    }

    const float Dd = (br ? Dr : Df)[d];
    const size_t rowbase = (size_t)b * LL + (size_t)seg * SEGL;
    const float* dp = gdelta + rowbase * DI + d;
    const float* xp = gxc + rowbase * DI + d;
    const float* bc = gxdbl + rowbase * 80 + 48;
    const float* gz = g_xz + (size_t)b * LL * 2 * DI + DI + d;

    __shared__ __align__(16) float sBC[32 * 32];

    for (int lc = 0; lc < SEGL; lc += 32) {
        __syncthreads();
        for (int i = tid; i < 32 * 32; i += 128) {
            int li = i >> 5, c = i & 31;
            sBC[i] = bc[(size_t)(lc + li) * 80 + c];
        }
        __syncthreads();
        for (int li = 0; li < 32; li++) {
            const int l = lc + li;
            const float delta = dp[(size_t)l * DI];
            const float x = xp[(size_t)l * DI];
            const float dx = delta * x;
            float bv[NST], cv[NST];
            const float4* q = (const float4*)&sBC[li * 32];
            ((float4*)bv)[0] = q[0]; ((float4*)bv)[1] = q[1];
            ((float4*)bv)[2] = q[2]; ((float4*)bv)[3] = q[3];
            ((float4*)cv)[0] = q[4]; ((float4*)cv)[1] = q[5];
            ((float4*)cv)[2] = q[6]; ((float4*)cv)[3] = q[7];
            float y = 0.f;
            if (fast) {
                const float e = __expf(-delta);
                float p = 1.f;
#pragma unroll
                for (int n = 0; n < NST; n++) {
                    p *= e;
                    h[n] = fmaf(p, h[n], dx * bv[n]);
                    y = fmaf(h[n], cv[n], y);
                }
            } else {
#pragma unroll
                for (int n = 0; n < NST; n++) {
                    float da = __expf(delta * An[n]);
                    h[n] = fmaf(da, h[n], dx * bv[n]);
                    y = fmaf(h[n], cv[n], y);
                }
            }
            const int gl = seg * SEGL + l;
            const int lo = br ? (LL - 1 - gl) : gl;
            const float zv = gz[(size_t)lo * 2 * DI];
            const float out = (y + x * Dd) * silu_f(zv);
            ys[((size_t)b * LL + lo) * DI + d] = out;
        }
    }
}

// ---------------- launch ----------------
extern "C" void kernel_launch(void* const* d_in, const int* in_sizes, int n_in,
                              void* d_out, int out_size) {
    const float* hidden     = (const float*)d_in[0];
    const float* in_proj_w  = (const float*)d_in[1];
    const float* conv_w     = (const float*)d_in[2];
    const float* conv_b     = (const float*)d_in[3];
    const float* x_proj_w   = (const float*)d_in[4];
    const float* dt_proj_w  = (const float*)d_in[5];
    const float* dt_proj_b  = (const float*)d_in[6];
    const float* A_log      = (const float*)d_in[7];
    const float* Dv         = (const float*)d_in[8];
    const float* conv_w_b   = (const float*)d_in[9];
    const float* conv_b_b   = (const float*)d_in[10];
    const float* x_proj_w_b = (const float*)d_in[11];
    const float* dt_proj_w_b= (const float*)d_in[12];
    const float* dt_proj_b_b= (const float*)d_in[13];
    const float* A_b_log    = (const float*)d_in[14];
    const float* D_b        = (const float*)d_in[15];
    const float* out_proj_w = (const float*)d_in[16];
    float* out = (float*)d_out;

    float *p_xz, *p_delta0, *p_delta1;
    cudaGetSymbolAddress((void**)&p_xz, g_xz);
    cudaGetSymbolAddress((void**)&p_delta0, g_delta0);
    cudaGetSymbolAddress((void**)&p_delta1, g_delta1);
    uint16_t *p_hidh, *p_hidl, *p_w1h, *p_w1l, *p_xwh, *p_xwl, *p_dtwh, *p_dtwl;
    uint16_t *p_owh, *p_owl, *p_xc0h, *p_xc0l, *p_xc1h, *p_xc1l, *p_ysh, *p_ysl;
    cudaGetSymbolAddress((void**)&p_hidh, g_hidh);
    cudaGetSymbolAddress((void**)&p_hidl, g_hidl);
    cudaGetSymbolAddress((void**)&p_w1h, g_w1h);
    cudaGetSymbolAddress((void**)&p_w1l, g_w1l);
    cudaGetSymbolAddress((void**)&p_xwh, g_xwh);
    cudaGetSymbolAddress((void**)&p_xwl, g_xwl);
    cudaGetSymbolAddress((void**)&p_dtwh, g_dtwh);
    cudaGetSymbolAddress((void**)&p_dtwl, g_dtwl);
    cudaGetSymbolAddress((void**)&p_owh, g_owh);
    cudaGetSymbolAddress((void**)&p_owl, g_owl);
    cudaGetSymbolAddress((void**)&p_xc0h, g_xc0h);
    cudaGetSymbolAddress((void**)&p_xc0l, g_xc0l);
    cudaGetSymbolAddress((void**)&p_xc1h, g_xc1h);
    cudaGetSymbolAddress((void**)&p_xc1l, g_xc1l);
    cudaGetSymbolAddress((void**)&p_ysh, g_ysh);
    cudaGetSymbolAddress((void**)&p_ysl, g_ysl);

    cudaFuncSetAttribute(gemm_mma_s<128>, cudaFuncAttributeMaxDynamicSharedMemorySize, 65536);
    cudaFuncSetAttribute(gemm_mma_s<64>,  cudaFuncAttributeMaxDynamicSharedMemorySize, 49152);
    cudaFuncSetAttribute(gemm_mma80b, cudaFuncAttributeMaxDynamicSharedMemorySize, MMA80_SMEM);
    cudaFuncSetAttribute(gemm_mma48b, cudaFuncAttributeMaxDynamicSharedMemorySize, 65536);

    const int M = BB * LL;  // 2048

    // 0) pre-split static tensors to bf16 hi/lo
    {
        SArgs sa{};
        int base = 0;
        auto add = [&](int k, const float* src, uint16_t* hi, uint16_t* lo, int n) {
            sa.s[k] = SSeg{src, hi, lo, base, n / 4};
            base += n / 4;
        };
        add(0, hidden,      p_hidh, p_hidl, M * DM);
        add(1, in_proj_w,   p_w1h,  p_w1l,  2 * DI * DM);
        add(2, x_proj_w,    p_xwh,            p_xwl,            80 * DI);
        add(3, x_proj_w_b,  p_xwh + 80 * DI,  p_xwl + 80 * DI,  80 * DI);
        add(4, dt_proj_w,   p_dtwh,           p_dtwl,           DI * DTR);
        add(5, dt_proj_w_b, p_dtwh + DI * DTR,p_dtwl + DI * DTR,DI * DTR);
        add(6, out_proj_w,  p_owh,  p_owl,  DM * DI);
        sa.total4 = base;
        split_many<<<(base + 255) / 256, 256>>>(sa);
    }

    // 1) xz = hidden @ in_proj_w^T
    {
        TBArgs a{};
        a.Ah = p_hidh; a.Al = p_hidl; a.Bh = p_w1h; a.Bl = p_w1l; a.C = p_xz;
        a.K = DM; a.lda = DM; a.ldb = DM; a.ldc = 2 * DI;
        gemm_mma_s<128><<<dim3(2 * DI / 128, M / 128), 256, 65536>>>(a);
    }

    // 2) conv + silu (+ bf16 split of xc)
    conv_silu_k<<<(unsigned)(((size_t)M * (DI / 4) + 255) / 256), 256>>>(
        conv_w, conv_b, conv_w_b, conv_b_b);

    // 3) x_dbl partials (split-K 4), both branches
    {
        G80B a{};
        a.Ah[0] = p_xc0h; a.Ah[1] = p_xc1h;
        a.Al[0] = p_xc0l; a.Al[1] = p_xc1l;
        gemm_mma80b<<<dim3(1, M / 64, 8), 256, MMA80_SMEM>>>(a);
    }

    // 4) combine partials -> f32 xdbl + bf16 split
    xdbl_combine<<<(2 * (M * 80 / 4) + 255) / 256, 256>>>();

    // 5) delta = softplus(dt @ dt_proj_w^T + bias)
    {
        G48B a{};
        a.C[0] = p_delta0; a.C[1] = p_delta1;
        a.bias[0] = dt_proj_b; a.bias[1] = dt_proj_b_b;
        gemm_mma48b<<<dim3(DI / 128, M / 128, 2), 256, 65536>>>(a);
    }

    // 6) scan pass A (segments 0..NSEG-2, both branches)
    scan_passA<<<dim3(DI / 128, NSEG - 1, 4), 128>>>(A_log, A_b_log);

    // 7) pass B: per-segment start states (parallel over state dim)
    scan_passB<<<(BB * 2 * DI * 4) / 128, 128>>>();

    // 8) pass C: re-scan + gate, both branches concurrent in one launch
    scan_passC<<<dim3(DI / 128, NSEG, 4), 128>>>(A_log, A_b_log, Dv, D_b);

    // 9) ys sum + bf16 split
    ys_split<<<(unsigned)(((size_t)M * DI / 4 + 255) / 256), 256>>>();

    // 10) out = ysum @ out_proj_w^T
    {
        TBArgs a{};
        a.Ah = p_ysh; a.Al = p_ysl; a.Bh = p_owh; a.Bl = p_owl; a.C = out;
        a.K = DI; a.lda = DI; a.ldb = DI; a.ldc = DM;
        gemm_mma_s<64><<<dim3(DM / 64, M / 128), 256, 49152>>>(a);
    }
}